// round 4
// baseline (speedup 1.0000x reference)
#include <cuda_runtime.h>

// EquivariantLayerNorm: N=262144 rows, DIM = 128 (scalar LN w/ weight+bias)
//                       + 64*3 (segment norms) + 32*5 (segment norms) = 480 fp32
// Pure HBM-streaming problem: ~1.0 GB total traffic, floor ~150us at ~6.5 TB/s.

#define S_DIM 128
#define DIM 480
#define ROWS_PER_BLOCK 16
#define THREADS 512
#define EPS 1e-5f

__global__ __launch_bounds__(THREADS) void eqln_kernel(
    const float* __restrict__ x,
    const float* __restrict__ weight,
    const float* __restrict__ bias,
    float* __restrict__ out)
{
    __shared__ float tile[ROWS_PER_BLOCK * DIM];   // 30720 B
    __shared__ float sw[S_DIM];
    __shared__ float sb[S_DIM];

    const int tid = threadIdx.x;
    if (tid < S_DIM) {
        sw[tid] = weight[tid];
        sb[tid] = bias[tid];
    }

    const long long base = (long long)blockIdx.x * (ROWS_PER_BLOCK * DIM);

    // ---- Coalesced vectorized load of 16 rows into shared ----
    // 16 rows * 480 floats = 7680 floats = 1920 float4
    const float4* __restrict__ src4 = reinterpret_cast<const float4*>(x + base);
    float4* t4 = reinterpret_cast<float4*>(tile);
    #pragma unroll
    for (int i = tid; i < ROWS_PER_BLOCK * DIM / 4; i += THREADS)
        t4[i] = src4[i];
    __syncthreads();

    const int warp = tid >> 5;
    const int lane = tid & 31;
    float* row = tile + warp * DIM;

    // ---- Scalar LayerNorm over first 128 elements (1 warp per row) ----
    // lane holds elements lane, lane+32, lane+64, lane+96 (conflict-free)
    float v0 = row[lane];
    float v1 = row[lane + 32];
    float v2 = row[lane + 64];
    float v3 = row[lane + 96];

    float s  = v0 + v1 + v2 + v3;
    float ss = v0 * v0 + v1 * v1 + v2 * v2 + v3 * v3;
    #pragma unroll
    for (int o = 16; o > 0; o >>= 1) {
        s  += __shfl_xor_sync(0xFFFFFFFFu, s,  o);
        ss += __shfl_xor_sync(0xFFFFFFFFu, ss, o);
    }
    const float mean = s * (1.0f / 128.0f);
    const float var  = ss * (1.0f / 128.0f) - mean * mean;
    const float inv  = rsqrtf(var + EPS);

    row[lane]      = (v0 - mean) * inv * sw[lane]      + sb[lane];
    row[lane + 32] = (v1 - mean) * inv * sw[lane + 32] + sb[lane + 32];
    row[lane + 64] = (v2 - mean) * inv * sw[lane + 64] + sb[lane + 64];
    row[lane + 96] = (v3 - mean) * inv * sw[lane + 96] + sb[lane + 96];

    // ---- Segment norms: 64 groups of d=3 (offset 128) + 32 groups of d=5 (offset 320) ----
    // Per-lane: groups lane and lane+32 are d=3; group lane+64 is d=5 (compile-time split).
    // Stride-3 / stride-5 lane addressing: gcd(3,32)=gcd(5,32)=1 -> conflict-free.

    #pragma unroll
    for (int gi = 0; gi < 2; gi++) {
        const int g = lane + gi * 32;            // 0..63
        float* p = row + S_DIM + 3 * g;
        float a = p[0], b = p[1], c = p[2];
        float m = (a + b + c) * (1.0f / 3.0f);
        float da = a - m, db = b - m, dc = c - m;
        float vr = (da * da + db * db + dc * dc) * (1.0f / 3.0f);
        float iv = rsqrtf(vr + EPS);
        p[0] = da * iv;
        p[1] = db * iv;
        p[2] = dc * iv;
    }
    {
        float* p = row + S_DIM + 64 * 3 + 5 * lane;  // groups of 5
        float a = p[0], b = p[1], c = p[2], d = p[3], e = p[4];
        float m = (a + b + c + d + e) * 0.2f;
        float da = a - m, db = b - m, dc = c - m, dd = d - m, de = e - m;
        float vr = (da * da + db * db + dc * dc + dd * dd + de * de) * 0.2f;
        float iv = rsqrtf(vr + EPS);
        p[0] = da * iv;
        p[1] = db * iv;
        p[2] = dc * iv;
        p[3] = dd * iv;
        p[4] = de * iv;
    }

    __syncthreads();

    // ---- Coalesced vectorized store ----
    float4* __restrict__ dst4 = reinterpret_cast<float4*>(out + base);
    #pragma unroll
    for (int i = tid; i < ROWS_PER_BLOCK * DIM / 4; i += THREADS)
        dst4[i] = t4[i];
}

extern "C" void kernel_launch(void* const* d_in, const int* in_sizes, int n_in,
                              void* d_out, int out_size)
{
    const float* x      = (const float*)d_in[0];
    const float* weight = (const float*)d_in[1];
    const float* bias   = (const float*)d_in[2];
    float* out = (float*)d_out;

    const int n_rows = in_sizes[0] / DIM;            // 262144
    const int grid = n_rows / ROWS_PER_BLOCK;        // 16384

    eqln_kernel<<<grid, THREADS>>>(x, weight, bias, out);
}